// round 13
// baseline (speedup 1.0000x reference)
#include <cuda_runtime.h>
#include <math.h>

#define B_ 4
#define C_ 512
#define L_ 2048
#define H_ 8
#define D_ 64
#define G_ 8
#define CPG_ (C_/G_)
#define EPS_ 1e-5f

typedef unsigned long long u64;

// ---------------- scratch ----------------------------------------------------
__device__ float g_s[B_ * C_];
__device__ float g_t[B_ * C_];
__device__ float g_qkv[(size_t)B_ * 3 * C_ * L_];
__device__ float g_att[(size_t)B_ * C_ * L_];

// ---------------- f32x2 helpers (value-based, no address-of) -----------------
__device__ __forceinline__ u64 pack2f(float lo, float hi) {
    u64 r; asm("mov.b64 %0, {%1, %2};" : "=l"(r) : "f"(lo), "f"(hi)); return r;
}
__device__ __forceinline__ void unpack2f(u64 v, float& lo, float& hi) {
    asm("mov.b64 {%0, %1}, %2;" : "=f"(lo), "=f"(hi) : "l"(v));
}
__device__ __forceinline__ u64 ffma2(u64 a, u64 b, u64 c) {
    u64 d; asm("fma.rn.f32x2 %0, %1, %2, %3;" : "=l"(d) : "l"(a), "l"(b), "l"(c)); return d;
}
__device__ __forceinline__ u64 fmul2(u64 a, u64 b) {
    u64 d; asm("mul.rn.f32x2 %0, %1, %2;" : "=l"(d) : "l"(a), "l"(b)); return d;
}

// ---------------- fast exp ---------------------------------------------------
__device__ __forceinline__ float fast_exp(float x) {
    float z = x * 1.4426950408889634f;
    z = fmaxf(z, -126.0f);
    float zi = rintf(z);
    int   i  = (int)zi;
    float y  = (z - zi) * 0.6931471805599453f;
    float r  = 8.3333333e-3f;
    r = fmaf(r, y, 4.1666667e-2f);
    r = fmaf(r, y, 1.6666667e-1f);
    r = fmaf(r, y, 0.5f);
    r = fmaf(r, y, 1.0f);
    r = fmaf(r, y, 1.0f);
    return __int_as_float(__float_as_int(r) + (i << 23));
}

// ---------------- 1) GroupNorm stats (proven) --------------------------------
__global__ __launch_bounds__(256) void gn_stats_kernel(
    const float* __restrict__ x, const float* __restrict__ nw,
    const float* __restrict__ nb)
{
    int bg = blockIdx.x;
    int b = bg / G_, g = bg % G_;
    const float* xp = x + ((size_t)b * C_ + (size_t)g * CPG_) * L_;
    const int NE = CPG_ * L_;
    float sum = 0.f, sq = 0.f;
    for (int i = threadIdx.x; i < NE; i += 256) {
        float v = xp[i];
        sum += v; sq = fmaf(v, v, sq);
    }
    __shared__ float ssum[256], ssq[256];
    ssum[threadIdx.x] = sum; ssq[threadIdx.x] = sq;
    __syncthreads();
    for (int off = 128; off > 0; off >>= 1) {
        if (threadIdx.x < off) {
            ssum[threadIdx.x] += ssum[threadIdx.x + off];
            ssq[threadIdx.x]  += ssq[threadIdx.x + off];
        }
        __syncthreads();
    }
    float mean = ssum[0] * (1.0f / NE);
    float var  = ssq[0] * (1.0f / NE) - mean * mean;
    float rstd = rsqrtf(var + EPS_);
    if (threadIdx.x < CPG_) {
        int c = g * CPG_ + threadIdx.x;
        float s = nw[c] * rstd;
        g_s[b * C_ + c] = s;
        g_t[b * C_ + c] = nb[c] - mean * s;
    }
}

// ---------------- 2) SGEMM with f32x2 inner loop -----------------------------
template<bool FOLD, bool RESID>
__global__ __launch_bounds__(256) void sgemm_wx_kernel(
    const float* __restrict__ A, const float* __restrict__ Bm,
    const float* __restrict__ bias, const float* __restrict__ resid,
    float* __restrict__ Cm, int M, int N, int K)
{
    int bz = blockIdx.z;
    const float* Bp = Bm + (size_t)bz * K * N;
    float*       Cp = Cm + (size_t)bz * M * N;
    const float* Rp = RESID ? (resid + (size_t)bz * M * N) : nullptr;
    const float* sp = FOLD ? (g_s + bz * C_) : nullptr;
    const float* tp = FOLD ? (g_t + bz * C_) : nullptr;

    int m0 = blockIdx.y * 128, n0 = blockIdx.x * 128;
    __shared__ float As[8][128];
    __shared__ float Bs[8][128];

    int tid = threadIdx.x;
    int tx = tid % 16, ty = tid / 16;
    int ar = tid / 2,  ac = (tid % 2) * 4;
    int bk = tid / 32, bn = (tid % 32) * 4;

    u64 accp[8][4];
#pragma unroll
    for (int i = 0; i < 8; i++)
#pragma unroll
        for (int e = 0; e < 4; e++) accp[i][e] = 0ull;

    for (int k0 = 0; k0 < K; k0 += 8) {
        float4 av = *(const float4*)&A[(size_t)(m0 + ar) * K + k0 + ac];
        float4 bv = *(const float4*)&Bp[(size_t)(k0 + bk) * N + n0 + bn];
        if (FOLD) {
            float ss = sp[k0 + bk], tt = tp[k0 + bk];
            bv.x = fmaf(bv.x, ss, tt); bv.y = fmaf(bv.y, ss, tt);
            bv.z = fmaf(bv.z, ss, tt); bv.w = fmaf(bv.w, ss, tt);
        }
        __syncthreads();
        As[ac + 0][ar] = av.x; As[ac + 1][ar] = av.y;
        As[ac + 2][ar] = av.z; As[ac + 3][ar] = av.w;
        *(float4*)&Bs[bk][bn] = bv;
        __syncthreads();
#pragma unroll
        for (int kk = 0; kk < 8; kk++) {
            float a[8], bb[8];
            *(float4*)&a[0]  = *(const float4*)&As[kk][ty * 8];
            *(float4*)&a[4]  = *(const float4*)&As[kk][ty * 8 + 4];
            *(float4*)&bb[0] = *(const float4*)&Bs[kk][tx * 8];
            *(float4*)&bb[4] = *(const float4*)&Bs[kk][tx * 8 + 4];
            u64 bp[4];
#pragma unroll
            for (int e = 0; e < 4; e++) bp[e] = pack2f(bb[2 * e], bb[2 * e + 1]);
#pragma unroll
            for (int i = 0; i < 8; i++) {
                u64 ap = pack2f(a[i], a[i]);
#pragma unroll
                for (int e = 0; e < 4; e++)
                    accp[i][e] = ffma2(ap, bp[e], accp[i][e]);
            }
        }
    }

#pragma unroll
    for (int i = 0; i < 8; i++) {
        float acc[8];
#pragma unroll
        for (int e = 0; e < 4; e++) unpack2f(accp[i][e], acc[2 * e], acc[2 * e + 1]);
        int m = m0 + ty * 8 + i;
        float bvv = bias[m];
        size_t base = (size_t)m * N + n0 + tx * 8;
#pragma unroll
        for (int v = 0; v < 2; v++) {
            float4 o;
            o.x = acc[v * 4 + 0] + bvv; o.y = acc[v * 4 + 1] + bvv;
            o.z = acc[v * 4 + 2] + bvv; o.w = acc[v * 4 + 3] + bvv;
            if (RESID) {
                float4 r = *(const float4*)&Rp[base + v * 4];
                o.x += r.x; o.y += r.y; o.z += r.z; o.w += r.w;
            }
            *(float4*)&Cp[base + v * 4] = o;
        }
    }
}

// ---------------- 3) flash v3: f32x2 S and PV loops --------------------------
// 128 threads: ty = tid>>4 (rows ty*8..+7), tx = tid&15 (keys/d tx*4..+3)
__global__ __launch_bounds__(128) void flash2_kernel()
{
    __shared__ float qd[64 * 64];   // q:  [d][row], pre-scaled
    __shared__ float kP[64 * 64];   // k:  [d][m]  -> later P: [row][m]
    __shared__ float vS[64 * 64];   // v^T: [m][d], float4-slot XOR swizzle by (m&15)

    int z = blockIdx.y, b = z / H_, h = z % H_;
    int l0 = blockIdx.x * 64;
    const float* qp = g_qkv + (size_t)b * 3 * C_ * L_ + (size_t)(h * D_) * L_;
    const float* kp = qp + (size_t)C_ * L_;
    const float* vp = kp + (size_t)C_ * L_;

    const int tid = threadIdx.x;
    const int ty = tid >> 4, tx = tid & 15;

    for (int e = tid; e < 4096; e += 128) {
        int d = e >> 6, r = e & 63;
        qd[d * 64 + r] = qp[(size_t)d * L_ + l0 + r] * 0.125f;
    }

    // outp[rp][j] = packed (out[2rp][j], out[2rp+1][j]); j = d-component
    u64 outp[4][4];
#pragma unroll
    for (int rp = 0; rp < 4; rp++)
#pragma unroll
        for (int j = 0; j < 4; j++) outp[rp][j] = 0ull;
    float mx[8], sml[8];
#pragma unroll
    for (int i = 0; i < 8; i++) { mx[i] = -1e30f; sml[i] = 0.f; }

    for (int m0 = 0; m0 < L_; m0 += 64) {
        __syncthreads();
        for (int e = tid; e < 4096; e += 128) {
            int d = e >> 6, m = e & 63;
            kP[d * 64 + m] = kp[(size_t)d * L_ + m0 + m];
            int slot = (d >> 2) ^ (m & 15);
            vS[m * 64 + slot * 4 + (d & 3)] = vp[(size_t)d * L_ + m0 + m];
        }
        __syncthreads();

        // ---- S = q . k^T  (packed row-pairs x 4 keys per thread) ----
        u64 sp[4][4];
#pragma unroll
        for (int rp = 0; rp < 4; rp++)
#pragma unroll
            for (int j = 0; j < 4; j++) sp[rp][j] = 0ull;
        {
            const float4* qd4 = (const float4*)qd;
            const float4* kd4 = (const float4*)kP;
#pragma unroll 8
            for (int d = 0; d < 64; d++) {
                float4 k4 = kd4[d * 16 + tx];
                float4 qa = qd4[d * 16 + ty * 2];
                float4 qb = qd4[d * 16 + ty * 2 + 1];
                u64 kb0 = pack2f(k4.x, k4.x), kb1 = pack2f(k4.y, k4.y);
                u64 kb2 = pack2f(k4.z, k4.z), kb3 = pack2f(k4.w, k4.w);
                u64 q01 = pack2f(qa.x, qa.y), q23 = pack2f(qa.z, qa.w);
                u64 q45 = pack2f(qb.x, qb.y), q67 = pack2f(qb.z, qb.w);
                sp[0][0] = ffma2(q01, kb0, sp[0][0]); sp[0][1] = ffma2(q01, kb1, sp[0][1]);
                sp[0][2] = ffma2(q01, kb2, sp[0][2]); sp[0][3] = ffma2(q01, kb3, sp[0][3]);
                sp[1][0] = ffma2(q23, kb0, sp[1][0]); sp[1][1] = ffma2(q23, kb1, sp[1][1]);
                sp[1][2] = ffma2(q23, kb2, sp[1][2]); sp[1][3] = ffma2(q23, kb3, sp[1][3]);
                sp[2][0] = ffma2(q45, kb0, sp[2][0]); sp[2][1] = ffma2(q45, kb1, sp[2][1]);
                sp[2][2] = ffma2(q45, kb2, sp[2][2]); sp[2][3] = ffma2(q45, kb3, sp[2][3]);
                sp[3][0] = ffma2(q67, kb0, sp[3][0]); sp[3][1] = ffma2(q67, kb1, sp[3][1]);
                sp[3][2] = ffma2(q67, kb2, sp[3][2]); sp[3][3] = ffma2(q67, kb3, sp[3][3]);
            }
        }
        float s[8][4];
#pragma unroll
        for (int rp = 0; rp < 4; rp++)
#pragma unroll
            for (int j = 0; j < 4; j++)
                unpack2f(sp[rp][j], s[2 * rp][j], s[2 * rp + 1][j]);

        // ---- online softmax ----
        float alpha[8];
#pragma unroll
        for (int i = 0; i < 8; i++) {
            float tm = fmaxf(fmaxf(s[i][0], s[i][1]), fmaxf(s[i][2], s[i][3]));
            tm = fmaxf(tm, __shfl_xor_sync(0xffffffffu, tm, 1));
            tm = fmaxf(tm, __shfl_xor_sync(0xffffffffu, tm, 2));
            tm = fmaxf(tm, __shfl_xor_sync(0xffffffffu, tm, 4));
            tm = fmaxf(tm, __shfl_xor_sync(0xffffffffu, tm, 8));
            float nm = fmaxf(tm, mx[i]);
            alpha[i] = fast_exp(mx[i] - nm);
            mx[i] = nm;
            float p0 = fast_exp(s[i][0] - nm);
            float p1 = fast_exp(s[i][1] - nm);
            float p2 = fast_exp(s[i][2] - nm);
            float p3 = fast_exp(s[i][3] - nm);
            s[i][0] = p0; s[i][1] = p1; s[i][2] = p2; s[i][3] = p3;
            float ps = (p0 + p1) + (p2 + p3);
            ps += __shfl_xor_sync(0xffffffffu, ps, 1);
            ps += __shfl_xor_sync(0xffffffffu, ps, 2);
            ps += __shfl_xor_sync(0xffffffffu, ps, 4);
            ps += __shfl_xor_sync(0xffffffffu, ps, 8);
            sml[i] = fmaf(sml[i], alpha[i], ps);
        }
#pragma unroll
        for (int rp = 0; rp < 4; rp++) {
            u64 alp = pack2f(alpha[2 * rp], alpha[2 * rp + 1]);
#pragma unroll
            for (int j = 0; j < 4; j++) outp[rp][j] = fmul2(outp[rp][j], alp);
        }
        __syncthreads();

        // ---- write P[row][m] into the (dead) k buffer ----
        {
            float4* Ps4 = (float4*)kP;
#pragma unroll
            for (int i = 0; i < 8; i++) {
                float4 pv;
                pv.x = s[i][0]; pv.y = s[i][1]; pv.z = s[i][2]; pv.w = s[i][3];
                Ps4[(ty * 8 + i) * 16 + tx] = pv;
            }
        }
        __syncthreads();

        // ---- out += P . V  (packed row-pairs x 4 d per thread) ----
        {
            const float4* Ps4 = (const float4*)kP;
            const float4* vS4 = (const float4*)vS;
#pragma unroll 4
            for (int mc = 0; mc < 16; mc++) {
                float4 pr0 = Ps4[(ty * 8 + 0) * 16 + mc];
                float4 pr1 = Ps4[(ty * 8 + 1) * 16 + mc];
                float4 pr2 = Ps4[(ty * 8 + 2) * 16 + mc];
                float4 pr3 = Ps4[(ty * 8 + 3) * 16 + mc];
                float4 pr4 = Ps4[(ty * 8 + 4) * 16 + mc];
                float4 pr5 = Ps4[(ty * 8 + 5) * 16 + mc];
                float4 pr6 = Ps4[(ty * 8 + 6) * 16 + mc];
                float4 pr7 = Ps4[(ty * 8 + 7) * 16 + mc];
#pragma unroll
                for (int mm = 0; mm < 4; mm++) {
                    int m = mc * 4 + mm;
                    float4 vf = vS4[m * 16 + (tx ^ (m & 15))];
                    float p0 = (mm == 0) ? pr0.x : (mm == 1) ? pr0.y : (mm == 2) ? pr0.z : pr0.w;
                    float p1 = (mm == 0) ? pr1.x : (mm == 1) ? pr1.y : (mm == 2) ? pr1.z : pr1.w;
                    float p2 = (mm == 0) ? pr2.x : (mm == 1) ? pr2.y : (mm == 2) ? pr2.z : pr2.w;
                    float p3 = (mm == 0) ? pr3.x : (mm == 1) ? pr3.y : (mm == 2) ? pr3.z : pr3.w;
                    float p4 = (mm == 0) ? pr4.x : (mm == 1) ? pr4.y : (mm == 2) ? pr4.z : pr4.w;
                    float p5 = (mm == 0) ? pr5.x : (mm == 1) ? pr5.y : (mm == 2) ? pr5.z : pr5.w;
                    float p6 = (mm == 0) ? pr6.x : (mm == 1) ? pr6.y : (mm == 2) ? pr6.z : pr6.w;
                    float p7 = (mm == 0) ? pr7.x : (mm == 1) ? pr7.y : (mm == 2) ? pr7.z : pr7.w;
                    u64 pp0 = pack2f(p0, p1), pp1 = pack2f(p2, p3);
                    u64 pp2 = pack2f(p4, p5), pp3 = pack2f(p6, p7);
                    u64 vb0 = pack2f(vf.x, vf.x), vb1 = pack2f(vf.y, vf.y);
                    u64 vb2 = pack2f(vf.z, vf.z), vb3 = pack2f(vf.w, vf.w);
                    outp[0][0] = ffma2(pp0, vb0, outp[0][0]);
                    outp[0][1] = ffma2(pp0, vb1, outp[0][1]);
                    outp[0][2] = ffma2(pp0, vb2, outp[0][2]);
                    outp[0][3] = ffma2(pp0, vb3, outp[0][3]);
                    outp[1][0] = ffma2(pp1, vb0, outp[1][0]);
                    outp[1][1] = ffma2(pp1, vb1, outp[1][1]);
                    outp[1][2] = ffma2(pp1, vb2, outp[1][2]);
                    outp[1][3] = ffma2(pp1, vb3, outp[1][3]);
                    outp[2][0] = ffma2(pp2, vb0, outp[2][0]);
                    outp[2][1] = ffma2(pp2, vb1, outp[2][1]);
                    outp[2][2] = ffma2(pp2, vb2, outp[2][2]);
                    outp[2][3] = ffma2(pp2, vb3, outp[2][3]);
                    outp[3][0] = ffma2(pp3, vb0, outp[3][0]);
                    outp[3][1] = ffma2(pp3, vb1, outp[3][1]);
                    outp[3][2] = ffma2(pp3, vb2, outp[3][2]);
                    outp[3][3] = ffma2(pp3, vb3, outp[3][3]);
                }
            }
        }
    }

    // ---- normalize + store att[d][l] ----
    float* op = g_att + (size_t)b * C_ * L_ + (size_t)(h * D_) * L_;
#pragma unroll
    for (int rp = 0; rp < 4; rp++) {
        float inv0 = 1.0f / sml[2 * rp];
        float inv1 = 1.0f / sml[2 * rp + 1];
        int la = l0 + ty * 8 + 2 * rp;
        int lb = la + 1;
#pragma unroll
        for (int j = 0; j < 4; j++) {
            float v0, v1;
            unpack2f(outp[rp][j], v0, v1);
            int d = tx * 4 + j;
            op[(size_t)d * L_ + la] = v0 * inv0;
            op[(size_t)d * L_ + lb] = v1 * inv1;
        }
    }
}

// ---------------- launch -----------------------------------------------------
extern "C" void kernel_launch(void* const* d_in, const int* in_sizes, int n_in,
                              void* d_out, int out_size)
{
    const float* x      = (const float*)d_in[0];
    const float* norm_w = (const float*)d_in[1];
    const float* norm_b = (const float*)d_in[2];
    const float* qkv_w  = (const float*)d_in[3];
    const float* qkv_b  = (const float*)d_in[4];
    const float* proj_w = (const float*)d_in[5];
    const float* proj_b = (const float*)d_in[6];
    float* out = (float*)d_out;

    float* qkv_ptr; cudaGetSymbolAddress((void**)&qkv_ptr, g_qkv);
    float* att_ptr; cudaGetSymbolAddress((void**)&att_ptr, g_att);

    gn_stats_kernel<<<B_ * G_, 256>>>(x, norm_w, norm_b);

    {
        dim3 grid(L_ / 128, (3 * C_) / 128, B_);
        sgemm_wx_kernel<true, false><<<grid, 256>>>(
            qkv_w, x, qkv_b, nullptr, qkv_ptr, 3 * C_, L_, C_);
    }

    {
        dim3 grid(L_ / 64, B_ * H_);
        flash2_kernel<<<grid, 128>>>();
    }

    {
        dim3 grid(L_ / 128, C_ / 128, B_);
        sgemm_wx_kernel<false, true><<<grid, 256>>>(
            proj_w, att_ptr, proj_b, x, out, C_, L_, C_);
    }
}